// round 7
// baseline (speedup 1.0000x reference)
#include <cuda_runtime.h>
#include <cstddef>

// FusionAdjacency: Af = rownorm( sigmoid(g)*scatter(s) + (1-sigmoid(g))*scatter(t) )
//
// R6: 2-chunk fill/scatter overlap using kernel boundaries as sync.
//   K1: fill rows [0,HALF)   || hist (rowsums) ; last hist block -> finalize
//   K2: fill rows [HALF,NN)  || scatter edges with r <  HALF (L2-warm lines)
//   K3:                         scatter edges with r >= HALF (L2-hot lines)
// Edge lists are scanned exactly twice for scatter (once per half).

#define NN   8192
#define HALF 4096

__device__ float g_rowsum[NN];   // zero at module load; finalize re-zeros
__device__ float g_rowinv[NN];
__device__ int   g_hist_done;    // zero at load; finalize block resets to 0

// ---------------------------------------------------------------- K1
// blocks [0, fillB): fill rows [0, HALF)
// blocks [fillB, gridDim): hist; last-arriving hist block finalizes.
__global__ __launch_bounds__(256) void k1_fill_hist(
        const int* __restrict__ rows_s, const float* __restrict__ vals_s, int Es,
        const int* __restrict__ rows_t, const float* __restrict__ vals_t, int Et,
        const float* __restrict__ gamma, float* __restrict__ out, int fillB) {
    if ((int)blockIdx.x < fillB) {
        // ---- fill first half ----
        const int tid = blockIdx.x * blockDim.x + threadIdx.x;
        const int stride = fillB * blockDim.x;
        float4* out4 = reinterpret_cast<float4*>(out);
        const int n4 = HALF * (NN / 4);
        const float4 z = make_float4(0.f, 0.f, 0.f, 0.f);
        for (int i = tid; i < n4; i += stride) out4[i] = z;
        return;
    }

    // ---- hist ----
    const int histB = gridDim.x - fillB;
    const int tid = ((int)blockIdx.x - fillB) * blockDim.x + threadIdx.x;
    const int stride = histB * blockDim.x;
    const float g = gamma[0];
    const float alpha = 1.0f / (1.0f + expf(-g));
    const float beta = 1.0f - alpha;
    for (int e = tid; e < Es; e += stride)
        atomicAdd(&g_rowsum[__ldg(&rows_s[e])], alpha * __ldg(&vals_s[e]));
    for (int e = tid; e < Et; e += stride)
        atomicAdd(&g_rowsum[__ldg(&rows_t[e])], beta * __ldg(&vals_t[e]));

    // ---- last-arriving hist block does finalize ----
    __syncthreads();
    __shared__ int s_last;
    if (threadIdx.x == 0) {
        __threadfence();
        int prev = atomicAdd(&g_hist_done, 1);
        s_last = (prev == histB - 1) ? 1 : 0;
    }
    __syncthreads();
    if (s_last) {
        __threadfence();  // acquire: make all blocks' rowsum atomics visible
        for (int i = threadIdx.x; i < NN; i += blockDim.x) {
            float s = g_rowsum[i];
            g_rowinv[i] = (s == 0.0f) ? 1.0f : (1.0f / s);
            g_rowsum[i] = 0.0f;    // ready for next graph replay
        }
        if (threadIdx.x == 0) g_hist_done = 0;
    }
}

// ---------------------------------------------------------------- K2 / K3
// K2: blocks [0, fillB) fill rows [HALF, NN); rest scatter r in [0, HALF).
// K3: fillB == 0; all blocks scatter r in [HALF, NN).
__global__ __launch_bounds__(256) void k2_fill_scatter(
        const int* __restrict__ rows_s, const int* __restrict__ cols_s,
        const float* __restrict__ vals_s, int Es,
        const int* __restrict__ rows_t, const int* __restrict__ cols_t,
        const float* __restrict__ vals_t, int Et,
        const float* __restrict__ gamma, float* __restrict__ out,
        int fillB, int scat_lo) {
    if ((int)blockIdx.x < fillB) {
        // ---- fill second half ----
        const int tid = blockIdx.x * blockDim.x + threadIdx.x;
        const int stride = fillB * blockDim.x;
        float4* out4 = reinterpret_cast<float4*>(out + (size_t)HALF * NN);
        const int n4 = HALF * (NN / 4);
        const float4 z = make_float4(0.f, 0.f, 0.f, 0.f);
        for (int i = tid; i < n4; i += stride) out4[i] = z;
        return;
    }

    // ---- scatter edges whose row is in [scat_lo, scat_lo + HALF) ----
    const int scatB = gridDim.x - fillB;
    const int tid = ((int)blockIdx.x - fillB) * blockDim.x + threadIdx.x;
    const int stride = scatB * blockDim.x;
    const float g = gamma[0];
    const float alpha = 1.0f / (1.0f + expf(-g));
    const float beta = 1.0f - alpha;
    const unsigned lo = (unsigned)scat_lo;

    for (int e = tid; e < Es; e += stride) {
        int r = __ldg(&rows_s[e]);
        if ((unsigned)(r - lo) < (unsigned)HALF) {
            float contrib = alpha * __ldg(&vals_s[e]) * g_rowinv[r];
            atomicAdd(&out[((size_t)r << 13) + __ldg(&cols_s[e])], contrib);
        }
    }
    for (int e = tid; e < Et; e += stride) {
        int r = __ldg(&rows_t[e]);
        if ((unsigned)(r - lo) < (unsigned)HALF) {
            float contrib = beta * __ldg(&vals_t[e]) * g_rowinv[r];
            atomicAdd(&out[((size_t)r << 13) + __ldg(&cols_t[e])], contrib);
        }
    }
}

// ---------------------------------------------------------------- launch
extern "C" void kernel_launch(void* const* d_in, const int* in_sizes, int n_in,
                              void* d_out, int out_size) {
    const int*   rows_s = (const int*)d_in[0];
    const int*   cols_s = (const int*)d_in[1];
    const float* vals_s = (const float*)d_in[2];
    const int*   rows_t = (const int*)d_in[3];
    const int*   cols_t = (const int*)d_in[4];
    const float* vals_t = (const float*)d_in[5];
    const float* gamma  = (const float*)d_in[6];
    float* out = (float*)d_out;

    const int Es = in_sizes[0];
    const int Et = in_sizes[3];
    const int T = 256;

    // K1: 2176 fill blocks + 192 hist blocks
    k1_fill_hist<<<2368, T>>>(rows_s, vals_s, Es, rows_t, vals_t, Et,
                              gamma, out, /*fillB=*/2176);

    // K2: 1792 fill blocks + 576 scatter blocks (first half rows)
    k2_fill_scatter<<<2368, T>>>(rows_s, cols_s, vals_s, Es,
                                 rows_t, cols_t, vals_t, Et,
                                 gamma, out, /*fillB=*/1792, /*scat_lo=*/0);

    // K3: all-scatter (second half rows, L2-hot from K2's fill)
    k2_fill_scatter<<<1024, T>>>(rows_s, cols_s, vals_s, Es,
                                 rows_t, cols_t, vals_t, Et,
                                 gamma, out, /*fillB=*/0, /*scat_lo=*/HALF);
}

// round 8
// speedup vs baseline: 1.2336x; 1.2336x over previous
#include <cuda_runtime.h>
#include <cstddef>

// FusionAdjacency: Af = rownorm( sigmoid(g)*scatter(s) + (1-sigmoid(g))*scatter(t) )
//
// R7: homogeneous fold + L2-staged two-phase fill.
//  K1: fill rows [0,XROW)  (96 MB, plain stores -> stays in L2) + hist folded
//      (every thread <=1 edge/list of fire-and-forget rowsum REDs).
//  K2: finalize rowinv, re-zero rowsum (replay-safe).
//  K3: fill rows [XROW,NN) (160 MB) + scatter edges r<XROW folded
//      (atomics hit L2-resident lines from K1, hidden under the fill).
//  K4: scatter edges r>=XROW (lines L2-hot from K3's fill).

#define NN   8192
#define XROW 3072              // 96 MB staged region, fits 126 MB L2

__device__ float g_rowsum[NN]; // zero at module load; K2 re-zeros each call
__device__ float g_rowinv[NN];

// ---------------------------------------------------------------- K1
__global__ __launch_bounds__(256) void k1_fill_lo_hist(
        const int* __restrict__ rows_s, const float* __restrict__ vals_s, int Es,
        const int* __restrict__ rows_t, const float* __restrict__ vals_t, int Et,
        const float* __restrict__ gamma, float* __restrict__ out) {
    const int tid = blockIdx.x * blockDim.x + threadIdx.x;
    const int stride = gridDim.x * blockDim.x;
    const float g = gamma[0];
    const float alpha = 1.0f / (1.0f + expf(-g));
    const float beta = 1.0f - alpha;

    // hist: <=1 edge per thread per list; RED (result unused) -> no stall
    for (int e = tid; e < Es; e += stride)
        atomicAdd(&g_rowsum[__ldg(&rows_s[e])], alpha * __ldg(&vals_s[e]));
    for (int e = tid; e < Et; e += stride)
        atomicAdd(&g_rowsum[__ldg(&rows_t[e])], beta * __ldg(&vals_t[e]));

    // fill rows [0, XROW): plain (evict-normal) stores keep lines in L2
    float4* out4 = reinterpret_cast<float4*>(out);
    const int n4 = XROW * (NN / 4);
    const float4 z = make_float4(0.f, 0.f, 0.f, 0.f);
    for (int i = tid; i < n4; i += stride) out4[i] = z;
}

// ---------------------------------------------------------------- K2
__global__ void k2_finalize() {
    int i = blockIdx.x * blockDim.x + threadIdx.x;
    if (i < NN) {
        float s = g_rowsum[i];
        g_rowinv[i] = (s == 0.0f) ? 1.0f : (1.0f / s);
        g_rowsum[i] = 0.0f;   // ready for next graph replay
    }
}

// ---------------------------------------------------------------- K3
__global__ __launch_bounds__(256) void k3_fill_hi_scatter_lo(
        const int* __restrict__ rows_s, const int* __restrict__ cols_s,
        const float* __restrict__ vals_s, int Es,
        const int* __restrict__ rows_t, const int* __restrict__ cols_t,
        const float* __restrict__ vals_t, int Et,
        const float* __restrict__ gamma, float* __restrict__ out) {
    const int tid = blockIdx.x * blockDim.x + threadIdx.x;
    const int stride = gridDim.x * blockDim.x;
    const float g = gamma[0];
    const float alpha = 1.0f / (1.0f + expf(-g));
    const float beta = 1.0f - alpha;

    // scatter edges with r < XROW: fire-and-forget REDs into L2-resident lines
    for (int e = tid; e < Es; e += stride) {
        int r = __ldg(&rows_s[e]);
        if (r < XROW) {
            float contrib = alpha * __ldg(&vals_s[e]) * g_rowinv[r];
            atomicAdd(&out[((size_t)r << 13) + __ldg(&cols_s[e])], contrib);
        }
    }
    for (int e = tid; e < Et; e += stride) {
        int r = __ldg(&rows_t[e]);
        if (r < XROW) {
            float contrib = beta * __ldg(&vals_t[e]) * g_rowinv[r];
            atomicAdd(&out[((size_t)r << 13) + __ldg(&cols_t[e])], contrib);
        }
    }

    // fill rows [XROW, NN): plain stores so lines stay resident for K4
    float4* out4 = reinterpret_cast<float4*>(out + (size_t)XROW * NN);
    const int n4 = (NN - XROW) * (NN / 4);
    const float4 z = make_float4(0.f, 0.f, 0.f, 0.f);
    for (int i = tid; i < n4; i += stride) out4[i] = z;
}

// ---------------------------------------------------------------- K4
__global__ __launch_bounds__(256) void k4_scatter_hi(
        const int* __restrict__ rows_s, const int* __restrict__ cols_s,
        const float* __restrict__ vals_s, int Es,
        const int* __restrict__ rows_t, const int* __restrict__ cols_t,
        const float* __restrict__ vals_t, int Et,
        const float* __restrict__ gamma, float* __restrict__ out) {
    const int tid = blockIdx.x * blockDim.x + threadIdx.x;
    const int stride = gridDim.x * blockDim.x;
    const float g = gamma[0];
    const float alpha = 1.0f / (1.0f + expf(-g));
    const float beta = 1.0f - alpha;

    for (int e = tid; e < Es; e += stride) {
        int r = __ldg(&rows_s[e]);
        if (r >= XROW) {
            float contrib = alpha * __ldg(&vals_s[e]) * g_rowinv[r];
            atomicAdd(&out[((size_t)r << 13) + __ldg(&cols_s[e])], contrib);
        }
    }
    for (int e = tid; e < Et; e += stride) {
        int r = __ldg(&rows_t[e]);
        if (r >= XROW) {
            float contrib = beta * __ldg(&vals_t[e]) * g_rowinv[r];
            atomicAdd(&out[((size_t)r << 13) + __ldg(&cols_t[e])], contrib);
        }
    }
}

// ---------------------------------------------------------------- launch
extern "C" void kernel_launch(void* const* d_in, const int* in_sizes, int n_in,
                              void* d_out, int out_size) {
    const int*   rows_s = (const int*)d_in[0];
    const int*   cols_s = (const int*)d_in[1];
    const float* vals_s = (const float*)d_in[2];
    const int*   rows_t = (const int*)d_in[3];
    const int*   cols_t = (const int*)d_in[4];
    const float* vals_t = (const float*)d_in[5];
    const float* gamma  = (const float*)d_in[6];
    float* out = (float*)d_out;

    const int Es = in_sizes[0];
    const int Et = in_sizes[3];
    const int T = 256;
    const int G = 2368;   // 16 blocks/SM

    k1_fill_lo_hist<<<G, T>>>(rows_s, vals_s, Es, rows_t, vals_t, Et,
                              gamma, out);

    k2_finalize<<<(NN + 255) / 256, 256>>>();

    k3_fill_hi_scatter_lo<<<G, T>>>(rows_s, cols_s, vals_s, Es,
                                    rows_t, cols_t, vals_t, Et, gamma, out);

    k4_scatter_hi<<<1024, T>>>(rows_s, cols_s, vals_s, Es,
                               rows_t, cols_t, vals_t, Et, gamma, out);
}

// round 9
// speedup vs baseline: 1.3224x; 1.0720x over previous
#include <cuda_runtime.h>
#include <cstddef>

// FusionAdjacency: Af = rownorm( sigmoid(g)*scatter(s) + (1-sigmoid(g))*scatter(t) )
//
// R8: R4 skeleton + dirty-L2 deferred-writeback overlap.
//  K1: fill rows [0,SPLIT) with __stcs (evict-first), rows [SPLIT,NN) with
//      plain stores (dirty lines stay in 126MB L2, writeback deferred past
//      kernel end); hist folded homogeneously (<=1 edge/thread/list REDs).
//  K2: finalize rowinv, re-zero rowsum (graph-replay safe).
//  K3: scatter all edges; tail-region atomics hit resident L2 lines while
//      the deferred writeback drains underneath the latency-bound scatter.

#define NN    8192
#define SPLIT 4608   // rows [SPLIT,NN) = 112 MB kept dirty in L2

__device__ float g_rowsum[NN];  // zero at module load; K2 re-zeros each call
__device__ float g_rowinv[NN];

// ---------------------------------------------------------------- K1
__global__ __launch_bounds__(256) void k1_fill_hist(
        const int* __restrict__ rows_s, const float* __restrict__ vals_s, int Es,
        const int* __restrict__ rows_t, const float* __restrict__ vals_t, int Et,
        const float* __restrict__ gamma, float* __restrict__ out) {
    const int tid = blockIdx.x * blockDim.x + threadIdx.x;
    const int stride = gridDim.x * blockDim.x;
    const float g = gamma[0];
    const float alpha = 1.0f / (1.0f + expf(-g));
    const float beta = 1.0f - alpha;

    // hist fold: <=1 edge per thread per list, fire-and-forget REDs
    for (int e = tid; e < Es; e += stride)
        atomicAdd(&g_rowsum[__ldg(&rows_s[e])], alpha * __ldg(&vals_s[e]));
    for (int e = tid; e < Et; e += stride)
        atomicAdd(&g_rowsum[__ldg(&rows_t[e])], beta * __ldg(&vals_t[e]));

    const float4 z = make_float4(0.f, 0.f, 0.f, 0.f);

    // head region: streaming stores, evicted (written back) during K1
    {
        float4* out4 = reinterpret_cast<float4*>(out);
        const int n4 = SPLIT * (NN / 4);
        for (int i = tid; i < n4; i += stride) __stcs(&out4[i], z);
    }
    // tail region: plain stores -> dirty lines parked in L2 (writeback
    // deferred; drains during K2/K3 while scatter runs)
    {
        float4* out4 = reinterpret_cast<float4*>(out + (size_t)SPLIT * NN);
        const int n4 = (NN - SPLIT) * (NN / 4);
        for (int i = tid; i < n4; i += stride) out4[i] = z;
    }
}

// ---------------------------------------------------------------- K2
__global__ void k2_finalize() {
    int i = blockIdx.x * blockDim.x + threadIdx.x;
    if (i < NN) {
        float s = g_rowsum[i];
        g_rowinv[i] = (s == 0.0f) ? 1.0f : (1.0f / s);
        g_rowsum[i] = 0.0f;   // ready for next graph replay
    }
}

// ---------------------------------------------------------------- K3
// One pass over both lists; two independent load->scale->RED chains per
// iteration; grid sized so all threads are resident in one wave.
__global__ __launch_bounds__(256) void k3_scatter(
        const int* __restrict__ rows_s, const int* __restrict__ cols_s,
        const float* __restrict__ vals_s, int Es,
        const int* __restrict__ rows_t, const int* __restrict__ cols_t,
        const float* __restrict__ vals_t, int Et,
        const float* __restrict__ gamma, float* __restrict__ out) {
    const float g = gamma[0];
    const float alpha = 1.0f / (1.0f + expf(-g));
    const float beta = 1.0f - alpha;
    const int tid = blockIdx.x * blockDim.x + threadIdx.x;
    const int stride = gridDim.x * blockDim.x;

    const int n = (Es > Et) ? Es : Et;
    for (int e = tid; e < n; e += stride) {
        int rs = 0, cs = 0;  float vs = 0.0f;
        if (e < Es) {
            rs = __ldg(&rows_s[e]);
            cs = __ldg(&cols_s[e]);
            vs = __ldg(&vals_s[e]);
        }
        int rt = 0, ct = 0;  float vt = 0.0f;
        if (e < Et) {
            rt = __ldg(&rows_t[e]);
            ct = __ldg(&cols_t[e]);
            vt = __ldg(&vals_t[e]);
        }
        float invs = g_rowinv[rs];
        float invt = g_rowinv[rt];
        if (e < Es) atomicAdd(&out[((size_t)rs << 13) + cs], alpha * vs * invs);
        if (e < Et) atomicAdd(&out[((size_t)rt << 13) + ct], beta * vt * invt);
    }
}

// ---------------------------------------------------------------- launch
extern "C" void kernel_launch(void* const* d_in, const int* in_sizes, int n_in,
                              void* d_out, int out_size) {
    const int*   rows_s = (const int*)d_in[0];
    const int*   cols_s = (const int*)d_in[1];
    const float* vals_s = (const float*)d_in[2];
    const int*   rows_t = (const int*)d_in[3];
    const int*   cols_t = (const int*)d_in[4];
    const float* vals_t = (const float*)d_in[5];
    const float* gamma  = (const float*)d_in[6];
    float* out = (float*)d_out;

    const int Es = in_sizes[0];
    const int Et = in_sizes[3];
    const int T = 256;

    // K1: full-chip fill + folded hist
    k1_fill_hist<<<2368, T>>>(rows_s, vals_s, Es, rows_t, vals_t, Et,
                              gamma, out);

    // K2: reciprocals
    k2_finalize<<<(NN + 255) / 256, 256>>>();

    // K3: scatter, ~one resident wave (148 SMs x 8 blocks of 256)
    k3_scatter<<<1184, T>>>(rows_s, cols_s, vals_s, Es,
                            rows_t, cols_t, vals_t, Et, gamma, out);
}